// round 13
// baseline (speedup 1.0000x reference)
#include <cuda_runtime.h>
#include <cuda_bf16.h>
#include <cuda_fp16.h>
#include <math.h>
#include <stdint.h>

// Problem constants (fixed shapes)
#define BATCH   4
#define NQ      5440
#define NV      5440
#define EMBED   256
#define NHEADS  8
#define NLEV    4
#define NPTS    4
#define HDIM    32
#define MTOT    (BATCH * NQ)          // 21760 = 170 * 128

// ---------------------------------------------------------------------------
// Scratch (static device globals — no allocation anywhere)
// ---------------------------------------------------------------------------
__device__ __half g_vh[MTOT * EMBED];                  // projected value (fp16)
__device__ float g_off[MTOT * EMBED];                  // sampling offsets
__device__ float g_aw[MTOT * 128];                     // attn logits

__device__ __nv_bfloat16 g_qhi[MTOT * EMBED],  g_qlo[MTOT * EMBED];   // query split
__device__ __nv_bfloat16 g_vhi[MTOT * EMBED],  g_vlo[MTOT * EMBED];   // value split
__device__ __nv_bfloat16 g_shi[MTOT * EMBED],  g_slo[MTOT * EMBED];   // sampled split

// transposed weight splits [N][K=256]
__device__ __nv_bfloat16 g_wvh[256 * 256], g_wvl[256 * 256];   // value_proj
__device__ __nv_bfloat16 g_wfh[256 * 256], g_wfl[256 * 256];   // offsets
__device__ __nv_bfloat16 g_wah[128 * 256], g_wal[128 * 256];   // attn
__device__ __nv_bfloat16 g_wuh[256 * 256], g_wul[256 * 256];   // out_proj

// ---------------------------------------------------------------------------
// Helpers
// ---------------------------------------------------------------------------
__device__ __forceinline__ uint32_t smem_u32(const void* p) {
    uint32_t a;
    asm("{ .reg .u64 t; cvta.to.shared.u64 t, %1; cvt.u32.u64 %0, t; }" : "=r"(a) : "l"(p));
    return a;
}

#define CP_ASYNC16(dst, src) \
    asm volatile("cp.async.cg.shared.global [%0], [%1], 16;" :: "r"(dst), "l"(src) : "memory")
#define CP_COMMIT() asm volatile("cp.async.commit_group;" ::: "memory")
#define CP_WAIT(n)  asm volatile("cp.async.wait_group %0;" :: "n"(n) : "memory")

__device__ __forceinline__ void ldm4(uint32_t* r, uint32_t addr) {
    asm volatile("ldmatrix.sync.aligned.m8n8.x4.shared.b16 {%0,%1,%2,%3}, [%4];"
                 : "=r"(r[0]), "=r"(r[1]), "=r"(r[2]), "=r"(r[3]) : "r"(addr));
}
__device__ __forceinline__ void mma16816(float* d, const uint32_t* a, const uint32_t* b) {
    asm volatile(
        "mma.sync.aligned.m16n8k16.row.col.f32.bf16.bf16.f32 "
        "{%0,%1,%2,%3}, {%4,%5,%6,%7}, {%8,%9}, {%0,%1,%2,%3};"
        : "+f"(d[0]), "+f"(d[1]), "+f"(d[2]), "+f"(d[3])
        : "r"(a[0]), "r"(a[1]), "r"(a[2]), "r"(a[3]), "r"(b[0]), "r"(b[1]));
}

// ---------------------------------------------------------------------------
// Fused activation decompose: value then query, f32 -> bf16 hi + lo residual
// ---------------------------------------------------------------------------
#define N4 (MTOT * EMBED / 4)
__global__ __launch_bounds__(256)
void decomp_act2(const float4* __restrict__ value, const float4* __restrict__ query,
                 uint2* __restrict__ vhi, uint2* __restrict__ vlo,
                 uint2* __restrict__ qhi, uint2* __restrict__ qlo) {
    int i = blockIdx.x * 256 + threadIdx.x;
    const float4* src; uint2 *hi, *lo;
    if (i < N4) { src = value; hi = vhi; lo = vlo; }
    else        { src = query; hi = qhi; lo = qlo; i -= N4; }
    float4 x = src[i];
    float v[4] = {x.x, x.y, x.z, x.w};
    union { __nv_bfloat16 b[4]; uint2 u; } H, L;
#pragma unroll
    for (int j = 0; j < 4; j++) {
        H.b[j] = __float2bfloat16(v[j]);
        L.b[j] = __float2bfloat16(v[j] - __bfloat162float(H.b[j]));
    }
    hi[i] = H.u;
    lo[i] = L.u;
}

// ---------------------------------------------------------------------------
// Fused weight decompose + transpose (all 4 weights in one launch).
// 32x32 smem tiles; coalesced reads AND writes. 224 tiles total.
// ---------------------------------------------------------------------------
__global__ __launch_bounds__(256)
void decomp_w_all(const float* __restrict__ Wv, const float* __restrict__ Wf,
                  const float* __restrict__ Wa, const float* __restrict__ Wu,
                  __nv_bfloat16* __restrict__ wvh, __nv_bfloat16* __restrict__ wvl,
                  __nv_bfloat16* __restrict__ wfh, __nv_bfloat16* __restrict__ wfl,
                  __nv_bfloat16* __restrict__ wah, __nv_bfloat16* __restrict__ wal,
                  __nv_bfloat16* __restrict__ wuh, __nv_bfloat16* __restrict__ wul) {
    __shared__ float tile[32][33];
    int id = blockIdx.x;
    const float* W; __nv_bfloat16 *hiT, *loT; int Nw, t;
    if (id < 64)       { W = Wv; hiT = wvh; loT = wvl; Nw = 256; t = id; }
    else if (id < 128) { W = Wf; hiT = wfh; loT = wfl; Nw = 256; t = id - 64; }
    else if (id < 160) { W = Wa; hiT = wah; loT = wal; Nw = 128; t = id - 128; }
    else               { W = Wu; hiT = wuh; loT = wul; Nw = 256; t = id - 160; }
    int ntiles_n = Nw >> 5;
    int tk = t / ntiles_n, tn = t % ntiles_n;
    int tx = threadIdx.x & 31, ty = threadIdx.x >> 5;   // 32 x 8

#pragma unroll
    for (int j = 0; j < 4; j++) {
        int k = tk * 32 + ty + j * 8;
        tile[ty + j * 8][tx] = W[(size_t)k * Nw + tn * 32 + tx];
    }
    __syncthreads();
#pragma unroll
    for (int j = 0; j < 4; j++) {
        int n = tn * 32 + ty + j * 8;
        float x = tile[tx][ty + j * 8];
        __nv_bfloat16 h = __float2bfloat16(x);
        size_t o = (size_t)n * 256 + tk * 32 + tx;
        hiT[o] = h;
        loT[o] = __float2bfloat16(x - __bfloat162float(h));
    }
}

// ---------------------------------------------------------------------------
// Tensor-core GEMM (legacy mma.sync path):
//   C[M,N] = A[M,256] @ W[256,N] + bias, bf16 3-product split, fp32 accum.
// Block 128x128, BK=32, 8 warps (4M x 2N), warp tile 32x64, 2-stage cp.async.
// If Ch != nullptr, output is written as fp16 to Ch instead of f32 to C.
// ---------------------------------------------------------------------------
#define STAGE_BYTES 32768            // 4 tiles x 8KB (Ahi,Alo,Bhi,Blo)
#define GEMM_SMEM   (2 * STAGE_BYTES)

__device__ void mma_gemm_body(char* sm,
                              const __nv_bfloat16* __restrict__ Ahi,
                              const __nv_bfloat16* __restrict__ Alo,
                              const __nv_bfloat16* __restrict__ Bhi,
                              const __nv_bfloat16* __restrict__ Blo,
                              const float* __restrict__ bias,
                              float* __restrict__ C, __half* __restrict__ Ch,
                              int N, int bm, int bn)
{
    const int t = threadIdx.x, lane = t & 31, warp = t >> 5;
    const int wm = (warp >> 1) * 32;
    const int wn = (warp & 1) * 64;

    const uint32_t sbase = smem_u32(sm);

    const char* gsrc[4] = {
        (const char*)(Ahi + (size_t)bm * 256), (const char*)(Alo + (size_t)bm * 256),
        (const char*)(Bhi + (size_t)bn * 256), (const char*)(Blo + (size_t)bn * 256)
    };
    const int lrow = t >> 2, lseg = t & 3;

    float acc[2][8][4];
#pragma unroll
    for (int a = 0; a < 2; a++)
#pragma unroll
        for (int b = 0; b < 8; b++)
#pragma unroll
            for (int d = 0; d < 4; d++) acc[a][b][d] = 0.0f;

    const int arow_l = lane & 15;
    const int aseg_l = lane >> 4;
    const int brow_l = (lane & 7) + ((lane >> 4) << 3);
    const int bseg_l = (lane >> 3) & 1;

#define LOAD_CHUNK(c, s) do {                                                   \
        uint32_t st_ = sbase + (s) * STAGE_BYTES;                               \
        _Pragma("unroll")                                                       \
        for (int it_ = 0; it_ < 2; it_++) {                                     \
            int row_ = lrow + it_ * 64;                                         \
            uint32_t so_ = (uint32_t)(row_ * 64 + ((lseg ^ (row_ & 3)) << 4));  \
            size_t go_ = (size_t)row_ * 512 + (size_t)(c) * 64 + lseg * 16;     \
            CP_ASYNC16(st_ +      0 + so_, gsrc[0] + go_);                      \
            CP_ASYNC16(st_ +  8192 + so_, gsrc[1] + go_);                       \
            CP_ASYNC16(st_ + 16384 + so_, gsrc[2] + go_);                       \
            CP_ASYNC16(st_ + 24576 + so_, gsrc[3] + go_);                       \
        }                                                                       \
        CP_COMMIT();                                                            \
    } while (0)

    LOAD_CHUNK(0, 0);

    for (int c = 0; c < 8; c++) {
        if (c < 7) { LOAD_CHUNK(c + 1, (c + 1) & 1); CP_WAIT(1); }
        else       { CP_WAIT(0); }
        __syncthreads();

        const uint32_t st = sbase + (c & 1) * STAGE_BYTES;
#pragma unroll
        for (int kk = 0; kk < 2; kk++) {
            uint32_t ah[2][4], al[2][4];
#pragma unroll
            for (int mt = 0; mt < 2; mt++) {
                int row = wm + mt * 16 + arow_l;
                int seg = kk * 2 + aseg_l;
                uint32_t ad = st + (uint32_t)(row * 64 + ((seg ^ (row & 3)) << 4));
                ldm4(ah[mt], ad);
                ldm4(al[mt], ad + 8192);
            }
#pragma unroll
            for (int np = 0; np < 4; np++) {
                int row = wn + np * 16 + brow_l;
                int seg = kk * 2 + bseg_l;
                uint32_t bd = st + 16384 + (uint32_t)(row * 64 + ((seg ^ (row & 3)) << 4));
                uint32_t bh[4], bl[4];
                ldm4(bh, bd);
                ldm4(bl, bd + 8192);
#pragma unroll
                for (int half = 0; half < 2; half++) {
                    int nt = np * 2 + half;
#pragma unroll
                    for (int mt = 0; mt < 2; mt++) {
                        mma16816(acc[mt][nt], ah[mt], bh + half * 2);  // hi*hi
                        mma16816(acc[mt][nt], ah[mt], bl + half * 2);  // hi*lo
                        mma16816(acc[mt][nt], al[mt], bh + half * 2);  // lo*hi
                    }
                }
            }
        }
        __syncthreads();
    }
#undef LOAD_CHUNK

    const int r0 = bm + wm + (lane >> 2);
    const int c0 = bn + wn + (lane & 3) * 2;
    if (Ch) {
#pragma unroll
        for (int nt = 0; nt < 8; nt++) {
            int col = c0 + nt * 8;
            float b0 = bias[col];
            float b1 = bias[col + 1];
#pragma unroll
            for (int mt = 0; mt < 2; mt++) {
                int row = r0 + mt * 16;
                __half2 p0 = __floats2half2_rn(acc[mt][nt][0] + b0, acc[mt][nt][1] + b1);
                __half2 p1 = __floats2half2_rn(acc[mt][nt][2] + b0, acc[mt][nt][3] + b1);
                *(__half2*)&Ch[(size_t)row * N + col]       = p0;
                *(__half2*)&Ch[(size_t)(row + 8) * N + col] = p1;
            }
        }
    } else {
#pragma unroll
        for (int nt = 0; nt < 8; nt++) {
            int col = c0 + nt * 8;
            float b0 = bias[col];
            float b1 = bias[col + 1];
#pragma unroll
            for (int mt = 0; mt < 2; mt++) {
                int row = r0 + mt * 16;
                float2 lo2, hi2;
                lo2.x = acc[mt][nt][0] + b0;
                lo2.y = acc[mt][nt][1] + b1;
                hi2.x = acc[mt][nt][2] + b0;
                hi2.y = acc[mt][nt][3] + b1;
                *(float2*)&C[(size_t)row * N + col]       = lo2;
                *(float2*)&C[(size_t)(row + 8) * N + col] = hi2;
            }
        }
    }
}

// Fused launch: value-proj (2 N-tiles, fp16 out) + offsets (2) + attn (1)
__global__ __launch_bounds__(256, 1)
void mma_gemm_fused(const __nv_bfloat16* valhi, const __nv_bfloat16* vallo,
                    const __nv_bfloat16* qhi,   const __nv_bfloat16* qlo,
                    const __nv_bfloat16* wvh,   const __nv_bfloat16* wvl,
                    const __nv_bfloat16* wfh,   const __nv_bfloat16* wfl,
                    const __nv_bfloat16* wah,   const __nv_bfloat16* wal,
                    const float* vb, const float* fb, const float* ab,
                    __half* Cv, float* Cf, float* Ca) {
    extern __shared__ char smem[];
    int bx = blockIdx.x, bm = blockIdx.y * 128;
    const __nv_bfloat16 *Ah, *Al, *Bh, *Bl;
    const float* bias; float* C; __half* Ch; int N, bn;
    if (bx < 2)      { Ah = valhi; Al = vallo; Bh = wvh; Bl = wvl; bias = vb; C = nullptr; Ch = Cv; N = 256; bn = bx * 128; }
    else if (bx < 4) { Ah = qhi;   Al = qlo;   Bh = wfh; Bl = wfl; bias = fb; C = Cf; Ch = nullptr; N = 256; bn = (bx - 2) * 128; }
    else             { Ah = qhi;   Al = qlo;   Bh = wah; Bl = wal; bias = ab; C = Ca; Ch = nullptr; N = 128; bn = 0; }
    mma_gemm_body(smem, Ah, Al, Bh, Bl, bias, C, Ch, N, bm, bn);
}

__global__ __launch_bounds__(256, 1)
void mma_gemm_out(const __nv_bfloat16* shi, const __nv_bfloat16* slo,
                  const __nv_bfloat16* wuh, const __nv_bfloat16* wul,
                  const float* ob, float* C) {
    extern __shared__ char smem[];
    mma_gemm_body(smem, shi, slo, wuh, wul, ob, C, nullptr, 256, blockIdx.y * 128, blockIdx.x * 128);
}

// ---------------------------------------------------------------------------
// Deformable sampling + softmax, v3: fp16 value + paired LDS.
// One warp per (b,q,head). Lanes <16 do softmax + bilinear setup, stage
// (byte-offset, weight) pairs in smem keyed [corner][point]. Gather: group
// g=lane>>3 handles corner g; lane reads 4 fp16 dims (8B). One LDS.128 feeds
// two gather iterations. Butterfly reduce; lanes 0-7 write hi, 8-15 lo.
// ---------------------------------------------------------------------------
__global__ __launch_bounds__(256)
void msda_sample(const __half* __restrict__ vbuf, const float* __restrict__ offbuf,
                 const float* __restrict__ awbuf, const float* __restrict__ refp,
                 __nv_bfloat16* __restrict__ shi, __nv_bfloat16* __restrict__ slo)
{
    __shared__ uint2 pairs[8][4][16];         // [warp][corner][point] = {byteoff, w}
    const unsigned FULL = 0xffffffffu;
    const int wwarp = threadIdx.x >> 5;
    const int lane  = threadIdx.x & 31;
    const int wg = blockIdx.x * 8 + wwarp;    // grid is exact: MTOT*NHEADS/8 blocks

    const int h  = wg & 7;
    const int bq = wg >> 3;
    const int b  = bq / NQ;

    // softmax over 16 (level,point) logits (4 butterfly rounds over lanes 0-15)
    float logit = -1e30f;
    if (lane < 16) logit = awbuf[(size_t)bq * 128 + h * 16 + lane];
    float m = logit;
#pragma unroll
    for (int o = 8; o >= 1; o >>= 1) m = fmaxf(m, __shfl_xor_sync(FULL, m, o));
    float e = (lane < 16) ? __expf(logit - m) : 0.0f;
    float s = e;
#pragma unroll
    for (int o = 8; o >= 1; o >>= 1) s += __shfl_xor_sync(FULL, s, o);
    float wgt = e / s;

    if (lane < 16) {
        int l = lane >> 2;
        int W = 64 >> l, H = 64 >> l;
        int base = (16384 - (16384 >> (2 * l))) / 3;
        float Wf = (float)W, Hf = (float)H;

        const float* rp = refp + ((size_t)bq * NLEV + l) * 2;
        const float2 op = *(const float2*)(offbuf + (size_t)bq * EMBED + h * 32 + 2 * lane);

        float px = (rp[0] + op.x * (1.0f / Wf)) * Wf - 0.5f;
        float py = (rp[1] + op.y * (1.0f / Hf)) * Hf - 0.5f;
        float x0f = floorf(px), y0f = floorf(py);
        float wx = px - x0f, wy = py - y0f;
        int x0 = (int)x0f, y0 = (int)y0f;

#pragma unroll
        for (int c = 0; c < 4; c++) {
            int dx = c & 1, dy = c >> 1;
            int xi = x0 + dx, yi = y0 + dy;
            bool valid = (xi >= 0) & (xi < W) & (yi >= 0) & (yi < H);
            int xc = min(max(xi, 0), W - 1);
            int yc = min(max(yi, 0), H - 1);
            float wc = (dx ? wx : 1.0f - wx) * (dy ? wy : 1.0f - wy);
            pairs[wwarp][c][lane] = make_uint2(
                (uint32_t)((base + yc * W + xc) << 9),        // byte offset (row=512B fp16)
                __float_as_uint(valid ? wgt * wc : 0.0f));
        }
    }
    __syncwarp(FULL);

    // gather: group g handles corner g; lane reads 4 fp16 dims (8B).
    const int g  = lane >> 3;
    const int li = lane & 7;
    const char* vb = (const char*)vbuf + (size_t)b * NV * 512 + h * 64 + li * 8;
    float4 acc = make_float4(0.0f, 0.0f, 0.0f, 0.0f);
#pragma unroll
    for (int ii = 0; ii < 8; ii++) {
        uint4 pq = *(const uint4*)&pairs[wwarp][g][ii * 2];   // two points
        {
            float w = __uint_as_float(pq.y);
            uint2 raw = *(const uint2*)(vb + pq.x);
            float2 f01 = __half22float2(*(__half2*)&raw.x);
            float2 f23 = __half22float2(*(__half2*)&raw.y);
            acc.x = fmaf(w, f01.x, acc.x);
            acc.y = fmaf(w, f01.y, acc.y);
            acc.z = fmaf(w, f23.x, acc.z);
            acc.w = fmaf(w, f23.y, acc.w);
        }
        {
            float w = __uint_as_float(pq.w);
            uint2 raw = *(const uint2*)(vb + pq.z);
            float2 f01 = __half22float2(*(__half2*)&raw.x);
            float2 f23 = __half22float2(*(__half2*)&raw.y);
            acc.x = fmaf(w, f01.x, acc.x);
            acc.y = fmaf(w, f01.y, acc.y);
            acc.z = fmaf(w, f23.x, acc.z);
            acc.w = fmaf(w, f23.y, acc.w);
        }
    }
    // reduce across the 4 groups (xor 8, 16)
#pragma unroll
    for (int o = 8; o <= 16; o <<= 1) {
        acc.x += __shfl_xor_sync(FULL, acc.x, o);
        acc.y += __shfl_xor_sync(FULL, acc.y, o);
        acc.z += __shfl_xor_sync(FULL, acc.z, o);
        acc.w += __shfl_xor_sync(FULL, acc.w, o);
    }

    if (lane < 16) {
        size_t o = (size_t)bq * EMBED + h * HDIM + li * 4;
        float v[4] = {acc.x, acc.y, acc.z, acc.w};
        union { __nv_bfloat16 b[4]; uint2 u; } P;
        if (lane < 8) {
#pragma unroll
            for (int j = 0; j < 4; j++) P.b[j] = __float2bfloat16(v[j]);
            *(uint2*)(shi + o) = P.u;
        } else {
#pragma unroll
            for (int j = 0; j < 4; j++) {
                __nv_bfloat16 hh = __float2bfloat16(v[j]);
                P.b[j] = __float2bfloat16(v[j] - __bfloat162float(hh));
            }
            *(uint2*)(slo + o) = P.u;
        }
    }
}

// ---------------------------------------------------------------------------
// kernel_launch
// ---------------------------------------------------------------------------
extern "C" void kernel_launch(void* const* d_in, const int* in_sizes, int n_in,
                              void* d_out, int out_size)
{
    const float* query   = (const float*)d_in[0];
    const float* value   = (const float*)d_in[1];
    const float* refp    = (const float*)d_in[2];
    const float* vproj_w = (const float*)d_in[3];
    const float* vproj_b = (const float*)d_in[4];
    const float* off_w   = (const float*)d_in[5];
    const float* off_b   = (const float*)d_in[6];
    const float* aw_w    = (const float*)d_in[7];
    const float* aw_b    = (const float*)d_in[8];
    const float* out_w   = (const float*)d_in[9];
    const float* out_b   = (const float*)d_in[10];
    float* out = (float*)d_out;

    float *off, *aw;
    __half* vh;
    __nv_bfloat16 *qhi, *qlo, *vhi, *vlo, *shi, *slo;
    __nv_bfloat16 *wvh, *wvl, *wfh, *wfl, *wah, *wal, *wuh, *wul;
    cudaGetSymbolAddress((void**)&vh,  g_vh);
    cudaGetSymbolAddress((void**)&off, g_off);
    cudaGetSymbolAddress((void**)&aw,  g_aw);
    cudaGetSymbolAddress((void**)&qhi, g_qhi); cudaGetSymbolAddress((void**)&qlo, g_qlo);
    cudaGetSymbolAddress((void**)&vhi, g_vhi); cudaGetSymbolAddress((void**)&vlo, g_vlo);
    cudaGetSymbolAddress((void**)&shi, g_shi); cudaGetSymbolAddress((void**)&slo, g_slo);
    cudaGetSymbolAddress((void**)&wvh, g_wvh); cudaGetSymbolAddress((void**)&wvl, g_wvl);
    cudaGetSymbolAddress((void**)&wfh, g_wfh); cudaGetSymbolAddress((void**)&wfl, g_wfl);
    cudaGetSymbolAddress((void**)&wah, g_wah); cudaGetSymbolAddress((void**)&wal, g_wal);
    cudaGetSymbolAddress((void**)&wuh, g_wuh); cudaGetSymbolAddress((void**)&wul, g_wul);

    cudaFuncSetAttribute(mma_gemm_fused, cudaFuncAttributeMaxDynamicSharedMemorySize, GEMM_SMEM);
    cudaFuncSetAttribute(mma_gemm_out,   cudaFuncAttributeMaxDynamicSharedMemorySize, GEMM_SMEM);

    // fused decomposes: activations (value+query) and all 4 weights
    decomp_act2<<<(2 * N4) / 256, 256>>>((const float4*)value, (const float4*)query,
                                         (uint2*)vhi, (uint2*)vlo, (uint2*)qhi, (uint2*)qlo);
    decomp_w_all<<<224, 256>>>(vproj_w, off_w, aw_w, out_w,
                               wvh, wvl, wfh, wfl, wah, wal, wuh, wul);

    // fused value/offsets/attn projections: 5 N-tiles x 170 M-tiles
    mma_gemm_fused<<<dim3(5, MTOT / 128), 256, GEMM_SMEM>>>(
        vhi, vlo, qhi, qlo, wvh, wvl, wfh, wfl, wah, wal,
        vproj_b, off_b, aw_b, vh, off, aw);

    // softmax + deformable bilinear sampling (fp16 value, bf16 split out)
    msda_sample<<<(MTOT * NHEADS) / 8, 256>>>(vh, off, aw, refp, shi, slo);

    // output projection straight into d_out
    mma_gemm_out<<<dim3(2, MTOT / 128), 256, GEMM_SMEM>>>(shi, slo, wuh, wul, out_b, out);
}